// round 3
// baseline (speedup 1.0000x reference)
#include <cuda_runtime.h>
#include <cuda_bf16.h>
#include <cstdint>

#define N_NODES 100000
#define N_EDGES 1600000
#define IN_DIM  512
#define HID_DIM 64

typedef unsigned long long u64;

// ---------------- scratch (static device globals: allocation-free) ----------
__device__ int   g_idx64;            // 1 if edge_index is int64, 0 if int32
__device__ float g_deg[N_NODES];
__device__ float g_dinv[N_NODES];
__device__ int   g_cnt[N_NODES];
__device__ int   g_rs[N_NODES + 1];
__device__ int   g_cur[N_NODES];
__device__ int   g_src[N_EDGES];
__device__ float g_w[N_EDGES];
__device__ float g_h[(size_t)N_NODES * HID_DIM];   // GEMM output (both layers)
__device__ float g_h2[(size_t)N_NODES * HID_DIM];  // layer-1 agg output

// ---------------- f32x2 helpers ---------------------------------------------
__device__ __forceinline__ u64 pack2(float lo, float hi) {
    u64 r; asm("mov.b64 %0,{%1,%2};" : "=l"(r) : "f"(lo), "f"(hi)); return r;
}
__device__ __forceinline__ u64 fma2(u64 a, u64 b, u64 c) {
    u64 d; asm("fma.rn.f32x2 %0,%1,%2,%3;" : "=l"(d) : "l"(a), "l"(b), "l"(c)); return d;
}
__device__ __forceinline__ float2 unpack2(u64 v) {
    float2 f; asm("mov.b64 {%0,%1},%2;" : "=f"(f.x), "=f"(f.y) : "l"(v)); return f;
}

// ---------------- edge-index dtype detection --------------------------------
// If dtype is int64 (values < 2^31), every odd 32-bit word of the buffer is 0.
// If int32, odd words are random node ids — all-zero over 128 samples is
// astronomically unlikely.
__global__ void detect_kernel(const int* __restrict__ ei32) {
    if (threadIdx.x == 0 && blockIdx.x == 0) {
        int all0 = 1;
        for (int i = 1; i < 256; i += 2)
            if (ei32[i] != 0) { all0 = 0; break; }
        g_idx64 = all0;
    }
}

__device__ __forceinline__ int load_idx(const void* ei, long long pos) {
    if (g_idx64) return (int)((const long long*)ei)[pos];
    return ((const int*)ei)[pos];
}

// ---------------- graph preprocessing ---------------------------------------
__global__ void init_kernel() {
    int i = blockIdx.x * blockDim.x + threadIdx.x;
    if (i < N_NODES) { g_deg[i] = 1.0f; g_cnt[i] = 0; }  // self-loop weight 1
}

__global__ void deg_hist_kernel(const void* __restrict__ ei,
                                const float* __restrict__ ew) {
    int e = blockIdx.x * blockDim.x + threadIdx.x;
    if (e >= N_EDGES) return;
    int d = load_idx(ei, (long long)N_EDGES + e);
    if ((unsigned)d < (unsigned)N_NODES) {
        atomicAdd(&g_deg[d], ew[e]);
        atomicAdd(&g_cnt[d], 1);
    }
}

__global__ void dinv_kernel() {
    int i = blockIdx.x * blockDim.x + threadIdx.x;
    if (i >= N_NODES) return;
    float d = g_deg[i];
    g_dinv[i] = (d > 0.0f) ? rsqrtf(d) : 0.0f;
}

// single-block exclusive scan of g_cnt -> g_rs, g_cur (1024 threads)
__global__ void scan_kernel(int n) {
    __shared__ int wsum[32];
    __shared__ int carry;
    int tid = threadIdx.x, lane = tid & 31, wid = tid >> 5;
    if (tid == 0) carry = 0;
    __syncthreads();
    for (int base = 0; base < n; base += 1024) {
        int i = base + tid;
        int v = (i < n) ? g_cnt[i] : 0;
        int x = v;
#pragma unroll
        for (int off = 1; off < 32; off <<= 1) {
            int y = __shfl_up_sync(0xffffffffu, x, off);
            if (lane >= off) x += y;
        }
        if (lane == 31) wsum[wid] = x;
        __syncthreads();
        if (wid == 0) {
            int s = wsum[lane];
#pragma unroll
            for (int off = 1; off < 32; off <<= 1) {
                int y = __shfl_up_sync(0xffffffffu, s, off);
                if (lane >= off) s += y;
            }
            wsum[lane] = s;
        }
        __syncthreads();
        int incl = x + (wid > 0 ? wsum[wid - 1] : 0);
        int excl = carry + incl - v;
        if (i < n) { g_rs[i] = excl; g_cur[i] = excl; }
        __syncthreads();                 // everyone done reading carry
        if (tid == 1023) carry += incl;  // block total (tail lanes are 0)
        __syncthreads();
    }
    if (tid == 0) g_rs[n] = carry;
}

__global__ void reorder_kernel(const void* __restrict__ ei,
                               const float* __restrict__ ew) {
    int e = blockIdx.x * blockDim.x + threadIdx.x;
    if (e >= N_EDGES) return;
    int s = load_idx(ei, e);
    int d = load_idx(ei, (long long)N_EDGES + e);
    if ((unsigned)d >= (unsigned)N_NODES) return;  // counted nowhere
    int p = atomicAdd(&g_cur[d], 1);
    if ((unsigned)s < (unsigned)N_NODES) {
        g_src[p] = s;
        g_w[p]   = g_dinv[s] * ew[e] * g_dinv[d];
    } else {  // keep slot consistent with g_cnt, contribute nothing
        g_src[p] = 0;
        g_w[p]   = 0.0f;
    }
}

// ---------------- GEMM: g_h[M,64] = X[M,K] @ W[K,64], f32x2 FFMA ------------
// Block: 128 rows x 64 cols, 256 threads, thread tile 8 rows x 4 cols.
// FROM_G_H2: input is the device-global g_h2 (layer 2); else external X.
template <int K, bool FROM_G_H2>
__global__ void __launch_bounds__(256) gemm64_kernel(
    const float* __restrict__ Xext, const float* __restrict__ W) {
    __shared__ __align__(16) float xs[16][132];  // [k][row], padded
    __shared__ __align__(16) float ws[16][64];   // [k][col]

    const float* X = FROM_G_H2 ? (const float*)g_h2 : Xext;
    float* out = g_h;

    const int M = N_NODES;
    int blockRow = blockIdx.x * 128;
    int t  = threadIdx.x;
    int tx = t & 15, ty = t >> 4;
    int r0 = ty * 8, c0 = tx * 4;

    u64 acc[4][4];
#pragma unroll
    for (int p = 0; p < 4; p++)
#pragma unroll
        for (int j = 0; j < 4; j++) acc[p][j] = 0ULL;

    for (int k0 = 0; k0 < K; k0 += 16) {
        // load X tile: 128 rows x 16 k, float4 along k
#pragma unroll
        for (int r = 0; r < 2; r++) {
            int id  = t + r * 256;   // 0..511
            int row = id >> 2;
            int q   = id & 3;
            float4 v = make_float4(0.f, 0.f, 0.f, 0.f);
            int grow = blockRow + row;
            if (grow < M)
                v = *(const float4*)(X + (size_t)grow * K + k0 + q * 4);
            xs[q * 4 + 0][row] = v.x;
            xs[q * 4 + 1][row] = v.y;
            xs[q * 4 + 2][row] = v.z;
            xs[q * 4 + 3][row] = v.w;
        }
        {   // load W tile: 16 k x 64 cols
            int k = t >> 4, q = t & 15;
            float4 v = *(const float4*)(W + (size_t)(k0 + k) * 64 + q * 4);
            *(float4*)&ws[k][q * 4] = v;
        }
        __syncthreads();
#pragma unroll
        for (int k = 0; k < 16; k++) {
            ulonglong2 A0 = *(const ulonglong2*)&xs[k][r0];      // rows r0..r0+3
            ulonglong2 A1 = *(const ulonglong2*)&xs[k][r0 + 4];  // rows r0+4..r0+7
            float4 wv = *(const float4*)&ws[k][c0];
            u64 w0 = pack2(wv.x, wv.x);
            u64 w1 = pack2(wv.y, wv.y);
            u64 w2 = pack2(wv.z, wv.z);
            u64 w3 = pack2(wv.w, wv.w);
            acc[0][0] = fma2(A0.x, w0, acc[0][0]);
            acc[0][1] = fma2(A0.x, w1, acc[0][1]);
            acc[0][2] = fma2(A0.x, w2, acc[0][2]);
            acc[0][3] = fma2(A0.x, w3, acc[0][3]);
            acc[1][0] = fma2(A0.y, w0, acc[1][0]);
            acc[1][1] = fma2(A0.y, w1, acc[1][1]);
            acc[1][2] = fma2(A0.y, w2, acc[1][2]);
            acc[1][3] = fma2(A0.y, w3, acc[1][3]);
            acc[2][0] = fma2(A1.x, w0, acc[2][0]);
            acc[2][1] = fma2(A1.x, w1, acc[2][1]);
            acc[2][2] = fma2(A1.x, w2, acc[2][2]);
            acc[2][3] = fma2(A1.x, w3, acc[2][3]);
            acc[3][0] = fma2(A1.y, w0, acc[3][0]);
            acc[3][1] = fma2(A1.y, w1, acc[3][1]);
            acc[3][2] = fma2(A1.y, w2, acc[3][2]);
            acc[3][3] = fma2(A1.y, w3, acc[3][3]);
        }
        __syncthreads();
    }
    // epilogue: pair p covers rows (r0+2p, r0+2p+1)
#pragma unroll
    for (int p = 0; p < 4; p++) {
        float2 f0 = unpack2(acc[p][0]);
        float2 f1 = unpack2(acc[p][1]);
        float2 f2 = unpack2(acc[p][2]);
        float2 f3 = unpack2(acc[p][3]);
        int row = blockRow + r0 + 2 * p;
        if (row < M)
            *(float4*)(out + (size_t)row * 64 + c0) =
                make_float4(f0.x, f1.x, f2.x, f3.x);
        if (row + 1 < M)
            *(float4*)(out + (size_t)(row + 1) * 64 + c0) =
                make_float4(f0.y, f1.y, f2.y, f3.y);
    }
}

// ---------------- aggregation: warp per node, CSR gather, no atomics --------
// Input is always g_h. RELU=true writes to g_h2; RELU=false writes to outp.
template <bool RELU>
__global__ void __launch_bounds__(256) agg_kernel(
    const float* __restrict__ bias, float2* __restrict__ outp) {
    const float2* H = (const float2*)g_h;
    float2* out = RELU ? (float2*)g_h2 : outp;

    int gw   = (blockIdx.x * blockDim.x + threadIdx.x) >> 5;
    int lane = threadIdx.x & 31;
    if (gw >= N_NODES) return;
    int node = gw;

    float di = g_dinv[node];
    float sn = di * di;  // self-loop norm
    float2 hv = H[(size_t)node * 32 + lane];
    float ax = sn * hv.x, ay = sn * hv.y;

    int b = g_rs[node], en = g_rs[node + 1];
    for (int i = b; i < en; i += 32) {
        int rem = en - i;
        int src = 0; float w = 0.f;
        if (lane < rem) { src = g_src[i + lane]; w = g_w[i + lane]; }
        int m = rem < 32 ? rem : 32;
        int j = 0;
        for (; j + 4 <= m; j += 4) {
            int   s0 = __shfl_sync(0xffffffffu, src, j);
            int   s1 = __shfl_sync(0xffffffffu, src, j + 1);
            int   s2 = __shfl_sync(0xffffffffu, src, j + 2);
            int   s3 = __shfl_sync(0xffffffffu, src, j + 3);
            float w0 = __shfl_sync(0xffffffffu, w, j);
            float w1 = __shfl_sync(0xffffffffu, w, j + 1);
            float w2 = __shfl_sync(0xffffffffu, w, j + 2);
            float w3 = __shfl_sync(0xffffffffu, w, j + 3);
            float2 x0 = H[(size_t)s0 * 32 + lane];
            float2 x1 = H[(size_t)s1 * 32 + lane];
            float2 x2 = H[(size_t)s2 * 32 + lane];
            float2 x3 = H[(size_t)s3 * 32 + lane];
            ax += w0 * x0.x; ay += w0 * x0.y;
            ax += w1 * x1.x; ay += w1 * x1.y;
            ax += w2 * x2.x; ay += w2 * x2.y;
            ax += w3 * x3.x; ay += w3 * x3.y;
        }
        for (; j < m; j++) {
            int   s0 = __shfl_sync(0xffffffffu, src, j);
            float w0 = __shfl_sync(0xffffffffu, w, j);
            float2 x0 = H[(size_t)s0 * 32 + lane];
            ax += w0 * x0.x; ay += w0 * x0.y;
        }
    }
    float2 bb = ((const float2*)bias)[lane];
    ax += bb.x; ay += bb.y;
    if (RELU) { ax = fmaxf(ax, 0.f); ay = fmaxf(ay, 0.f); }
    out[(size_t)node * 32 + lane] = make_float2(ax, ay);
}

// ---------------- launch -----------------------------------------------------
extern "C" void kernel_launch(void* const* d_in, const int* in_sizes, int n_in,
                              void* d_out, int out_size) {
    const float* x   = (const float*)d_in[0];
    const void*  ei  = d_in[1];                 // int32 or int64, detected on device
    const float* ew  = (const float*)d_in[2];
    const float* W1  = (const float*)d_in[3];
    const float* b1  = (const float*)d_in[4];
    const float* W2  = (const float*)d_in[5];
    const float* b2  = (const float*)d_in[6];
    float*       out = (float*)d_out;

    const int TPB = 256;
    int nBlocksN = (N_NODES + TPB - 1) / TPB;
    int nBlocksE = (N_EDGES + TPB - 1) / TPB;
    int gemmBlocks = (N_NODES + 127) / 128;
    int aggBlocks  = (N_NODES + 7) / 8;  // 8 warps/block, warp per node

    // CSR build (reused for both layers)
    detect_kernel<<<1, 32>>>((const int*)ei);
    init_kernel<<<nBlocksN, TPB>>>();
    deg_hist_kernel<<<nBlocksE, TPB>>>(ei, ew);
    dinv_kernel<<<nBlocksN, TPB>>>();
    scan_kernel<<<1, 1024>>>(N_NODES);
    reorder_kernel<<<nBlocksE, TPB>>>(ei, ew);

    // layer 1: g_h = x @ W1 ; g_h2 = relu(A_norm g_h + b1)
    gemm64_kernel<IN_DIM, false><<<gemmBlocks, TPB>>>(x, W1);
    agg_kernel<true><<<aggBlocks, TPB>>>(b1, nullptr);

    // layer 2: g_h = g_h2 @ W2 ; out = A_norm g_h + b2
    gemm64_kernel<HID_DIM, true><<<gemmBlocks, TPB>>>(nullptr, W2);
    agg_kernel<false><<<aggBlocks, TPB>>>(b2, (float2*)out);
}

// round 6
// speedup vs baseline: 1.2716x; 1.2716x over previous
#include <cuda_runtime.h>
#include <cuda_bf16.h>
#include <cstdint>

#define N_NODES 100000
#define N_EDGES 1600000
#define IN_DIM  512
#define HID_DIM 64
#define NSB ((N_NODES + 1023) / 1024)   // 98 scan blocks

// ---------------- scratch (static device globals: allocation-free) ----------
__device__ int   g_idx64;
__device__ float g_deg[N_NODES];
__device__ float g_dinv[N_NODES];
__device__ int   g_cnt[N_NODES];
__device__ int   g_rs[N_NODES + 1];
__device__ int   g_cur[N_NODES];
__device__ int   g_bsum[NSB];
__device__ int   g_boff[NSB];
__device__ int   g_src[N_EDGES];
__device__ float g_w[N_EDGES];
__device__ float g_h[(size_t)N_NODES * HID_DIM];   // GEMM output (both layers)
__device__ float g_h2[(size_t)N_NODES * HID_DIM];  // layer-1 agg output
// tf32 hi/lo split of W, stored [n][k] (B operand)
__device__ float g_b1hi[64 * IN_DIM];
__device__ float g_b1lo[64 * IN_DIM];
__device__ float g_b2hi[64 * HID_DIM];
__device__ float g_b2lo[64 * HID_DIM];

// ---------------- mma / tf32 helpers -----------------------------------------
__device__ __forceinline__ uint32_t f2tf(float x) {
    uint32_t r; asm("cvt.rna.tf32.f32 %0, %1;" : "=r"(r) : "f"(x)); return r;
}
__device__ __forceinline__ void mma_tf32(float* c,
                                         uint32_t a0, uint32_t a1, uint32_t a2, uint32_t a3,
                                         uint32_t b0, uint32_t b1) {
    asm("mma.sync.aligned.m16n8k8.row.col.f32.tf32.tf32.f32 "
        "{%0,%1,%2,%3},{%4,%5,%6,%7},{%8,%9},{%0,%1,%2,%3};"
        : "+f"(c[0]), "+f"(c[1]), "+f"(c[2]), "+f"(c[3])
        : "r"(a0), "r"(a1), "r"(a2), "r"(a3), "r"(b0), "r"(b1));
}

// ---------------- edge-index dtype detection --------------------------------
__global__ void detect_kernel(const int* __restrict__ ei32) {
    if (threadIdx.x == 0 && blockIdx.x == 0) {
        int all0 = 1;
        for (int i = 1; i < 256; i += 2)
            if (ei32[i] != 0) { all0 = 0; break; }
        g_idx64 = all0;
    }
}
__device__ __forceinline__ int load_idx(const void* ei, long long pos) {
    if (g_idx64) return (int)((const long long*)ei)[pos];
    return ((const int*)ei)[pos];
}

// ---------------- graph preprocessing ---------------------------------------
__global__ void init_kernel() {
    int i = blockIdx.x * blockDim.x + threadIdx.x;
    if (i < N_NODES) { g_deg[i] = 1.0f; g_cnt[i] = 0; }
}

__global__ void deg_hist_kernel(const void* __restrict__ ei,
                                const float* __restrict__ ew) {
    int e = blockIdx.x * blockDim.x + threadIdx.x;
    if (e >= N_EDGES) return;
    int d = load_idx(ei, (long long)N_EDGES + e);
    if ((unsigned)d < (unsigned)N_NODES) {
        atomicAdd(&g_deg[d], ew[e]);
        atomicAdd(&g_cnt[d], 1);
    }
}

__global__ void dinv_kernel() {
    int i = blockIdx.x * blockDim.x + threadIdx.x;
    if (i >= N_NODES) return;
    float d = g_deg[i];
    g_dinv[i] = (d > 0.0f) ? rsqrtf(d) : 0.0f;
}

// 3-phase multiblock scan of g_cnt -> g_rs (exclusive), g_cur copy
__global__ void scan1_kernel() {
    __shared__ int ws[32];
    int b = blockIdx.x, tid = threadIdx.x, lane = tid & 31, wid = tid >> 5;
    int i = b * 1024 + tid;
    int v = (i < N_NODES) ? g_cnt[i] : 0;
    int x = v;
#pragma unroll
    for (int off = 1; off < 32; off <<= 1) {
        int y = __shfl_up_sync(0xffffffffu, x, off);
        if (lane >= off) x += y;
    }
    if (lane == 31) ws[wid] = x;
    __syncthreads();
    if (wid == 0) {
        int s = ws[lane];
#pragma unroll
        for (int off = 1; off < 32; off <<= 1) {
            int y = __shfl_up_sync(0xffffffffu, s, off);
            if (lane >= off) s += y;
        }
        ws[lane] = s;
    }
    __syncthreads();
    int incl = x + (wid > 0 ? ws[wid - 1] : 0);
    if (i < N_NODES) g_rs[i] = incl - v;       // block-local exclusive
    if (tid == 1023) g_bsum[b] = incl;         // block total
}

__global__ void scan2_kernel() {
    __shared__ int ws[4];
    int tid = threadIdx.x, lane = tid & 31, wid = tid >> 5;
    int v = (tid < NSB) ? g_bsum[tid] : 0;
    int x = v;
#pragma unroll
    for (int off = 1; off < 32; off <<= 1) {
        int y = __shfl_up_sync(0xffffffffu, x, off);
        if (lane >= off) x += y;
    }
    if (lane == 31) ws[wid] = x;
    __syncthreads();
    if (tid == 0) {
        int a = 0;
        for (int j = 0; j < 4; j++) { int t = ws[j]; ws[j] = a; a += t; }
    }
    __syncthreads();
    int excl = x - v + ws[wid];
    if (tid < NSB) g_boff[tid] = excl;
    if (tid == NSB - 1) g_rs[N_NODES] = excl + v;
}

__global__ void scan3_kernel() {
    int i = blockIdx.x * 1024 + threadIdx.x;
    if (i < N_NODES) {
        int r = g_rs[i] + g_boff[blockIdx.x];
        g_rs[i] = r;
        g_cur[i] = r;
    }
}

__global__ void reorder_kernel(const void* __restrict__ ei,
                               const float* __restrict__ ew) {
    int e = blockIdx.x * blockDim.x + threadIdx.x;
    if (e >= N_EDGES) return;
    int s = load_idx(ei, e);
    int d = load_idx(ei, (long long)N_EDGES + e);
    if ((unsigned)d >= (unsigned)N_NODES) return;
    int p = atomicAdd(&g_cur[d], 1);
    if ((unsigned)s < (unsigned)N_NODES) {
        g_src[p] = s;
        g_w[p]   = g_dinv[s] * ew[e] * g_dinv[d];
    } else {
        g_src[p] = 0;
        g_w[p]   = 0.0f;
    }
}

// ---------------- W -> tf32 hi/lo, transposed to [n][k] ---------------------
__global__ void convw_kernel(const float* __restrict__ W1,
                             const float* __restrict__ W2) {
    int i = blockIdx.x * blockDim.x + threadIdx.x;
    if (i < IN_DIM * 64) {
        int k = i / 64, n = i % 64;
        float w = W1[i];
        uint32_t h = f2tf(w);
        float hf = __uint_as_float(h);
        g_b1hi[n * IN_DIM + k] = hf;
        g_b1lo[n * IN_DIM + k] = __uint_as_float(f2tf(w - hf));
    }
    if (i < HID_DIM * 64) {
        int k = i / 64, n = i % 64;
        float w = W2[i];
        uint32_t h = f2tf(w);
        float hf = __uint_as_float(h);
        g_b2hi[n * HID_DIM + k] = hf;
        g_b2lo[n * HID_DIM + k] = __uint_as_float(f2tf(w - hf));
    }
}

// ---------------- TF32 mma GEMM: g_h[M,64] = X[M,K] @ W[K,64] ----------------
// Block: 128 threads (4 warps), tile 128 rows x 64 cols. Warp: 32 rows (2 m16
// tiles) x 64 cols (8 n8 tiles). K chunked by 32. 3-pass tf32 hi/lo split.
// Weight arrays are selected INSIDE device code (never passed from host).
template <int K, bool FROM_G_H2>
__global__ void __launch_bounds__(128) mma_gemm_kernel(
    const float* __restrict__ Xext) {
    __shared__ float4 xs4[8][129];   // [k>>2][row], component k&3
    __shared__ float  wsh[64][36];   // [n][k] hi
    __shared__ float  wsl[64][36];   // [n][k] lo

    const float* X   = FROM_G_H2 ? (const float*)g_h2 : Xext;
    const float* Bhi = (K == IN_DIM) ? (const float*)g_b1hi : (const float*)g_b2hi;
    const float* Blo = (K == IN_DIM) ? (const float*)g_b1lo : (const float*)g_b2lo;

    const int M = N_NODES;
    int t = threadIdx.x, wid = t >> 5, lane = t & 31;
    int rowBase = blockIdx.x * 128;

    float acc[2][8][4] = {};

    for (int ch = 0; ch < K / 32; ch++) {
        int k0 = ch * 32;
        __syncthreads();
        // X tile: 128 rows x 32 k (coalesced float4 per row-segment)
#pragma unroll
        for (int it = 0; it < 8; it++) {
            int id = t + it * 128;
            int row = id >> 3, q = id & 7;
            int gr = rowBase + row;
            float4 v = make_float4(0.f, 0.f, 0.f, 0.f);
            if (gr < M) v = *(const float4*)(X + (size_t)gr * K + k0 + q * 4);
            xs4[q][row] = v;
        }
        // B tiles: 64 n x 32 k, hi + lo
#pragma unroll
        for (int it = 0; it < 4; it++) {
            int id = t + it * 128;
            int n = id >> 3, q = id & 7;
            *(float4*)&wsh[n][q * 4] = *(const float4*)(Bhi + (size_t)n * K + k0 + q * 4);
            *(float4*)&wsl[n][q * 4] = *(const float4*)(Blo + (size_t)n * K + k0 + q * 4);
        }
        __syncthreads();

#pragma unroll
        for (int ks = 0; ks < 4; ks++) {
            uint32_t ah[2][4], al[2][4];
#pragma unroll
            for (int mt = 0; mt < 2; mt++) {
                int r = wid * 32 + mt * 16 + (lane >> 2);
                int c = lane & 3;
                float x0 = ((const float*)&xs4[ks * 2][r])[c];
                float x1 = ((const float*)&xs4[ks * 2][r + 8])[c];
                float x2 = ((const float*)&xs4[ks * 2 + 1][r])[c];
                float x3 = ((const float*)&xs4[ks * 2 + 1][r + 8])[c];
                ah[mt][0] = f2tf(x0); al[mt][0] = f2tf(x0 - __uint_as_float(ah[mt][0]));
                ah[mt][1] = f2tf(x1); al[mt][1] = f2tf(x1 - __uint_as_float(ah[mt][1]));
                ah[mt][2] = f2tf(x2); al[mt][2] = f2tf(x2 - __uint_as_float(ah[mt][2]));
                ah[mt][3] = f2tf(x3); al[mt][3] = f2tf(x3 - __uint_as_float(ah[mt][3]));
            }
#pragma unroll
            for (int nt = 0; nt < 8; nt++) {
                int col = nt * 8 + (lane >> 2);
                int kk = ks * 8 + (lane & 3);
                uint32_t bh0 = __float_as_uint(wsh[col][kk]);
                uint32_t bh1 = __float_as_uint(wsh[col][kk + 4]);
                uint32_t bl0 = __float_as_uint(wsl[col][kk]);
                uint32_t bl1 = __float_as_uint(wsl[col][kk + 4]);
#pragma unroll
                for (int mt = 0; mt < 2; mt++) {
                    mma_tf32(acc[mt][nt], ah[mt][0], ah[mt][1], ah[mt][2], ah[mt][3], bh0, bh1);
                    mma_tf32(acc[mt][nt], ah[mt][0], ah[mt][1], ah[mt][2], ah[mt][3], bl0, bl1);
                    mma_tf32(acc[mt][nt], al[mt][0], al[mt][1], al[mt][2], al[mt][3], bh0, bh1);
                }
            }
        }
    }
    // epilogue
#pragma unroll
    for (int mt = 0; mt < 2; mt++) {
        int r0g = rowBase + wid * 32 + mt * 16 + (lane >> 2);
#pragma unroll
        for (int nt = 0; nt < 8; nt++) {
            int col = nt * 8 + (lane & 3) * 2;
            if (r0g < M)
                *(float2*)(g_h + (size_t)r0g * 64 + col) =
                    make_float2(acc[mt][nt][0], acc[mt][nt][1]);
            if (r0g + 8 < M)
                *(float2*)(g_h + (size_t)(r0g + 8) * 64 + col) =
                    make_float2(acc[mt][nt][2], acc[mt][nt][3]);
        }
    }
}

// ---------------- aggregation: warp per node, CSR gather, no atomics --------
template <bool RELU>
__global__ void __launch_bounds__(256) agg_kernel(
    const float* __restrict__ bias, float2* __restrict__ outp) {
    const float2* H = (const float2*)g_h;
    float2* out = RELU ? (float2*)g_h2 : outp;

    int gw   = (blockIdx.x * blockDim.x + threadIdx.x) >> 5;
    int lane = threadIdx.x & 31;
    if (gw >= N_NODES) return;
    int node = gw;

    float di = g_dinv[node];
    float sn = di * di;
    float2 hv = H[(size_t)node * 32 + lane];
    float ax = sn * hv.x, ay = sn * hv.y;

    int b = g_rs[node], en = g_rs[node + 1];
    for (int i = b; i < en; i += 32) {
        int rem = en - i;
        int src = 0; float w = 0.f;
        if (lane < rem) { src = g_src[i + lane]; w = g_w[i + lane]; }
        int m = rem < 32 ? rem : 32;
        int j = 0;
        for (; j + 4 <= m; j += 4) {
            int   s0 = __shfl_sync(0xffffffffu, src, j);
            int   s1 = __shfl_sync(0xffffffffu, src, j + 1);
            int   s2 = __shfl_sync(0xffffffffu, src, j + 2);
            int   s3 = __shfl_sync(0xffffffffu, src, j + 3);
            float w0 = __shfl_sync(0xffffffffu, w, j);
            float w1 = __shfl_sync(0xffffffffu, w, j + 1);
            float w2 = __shfl_sync(0xffffffffu, w, j + 2);
            float w3 = __shfl_sync(0xffffffffu, w, j + 3);
            float2 x0 = H[(size_t)s0 * 32 + lane];
            float2 x1 = H[(size_t)s1 * 32 + lane];
            float2 x2 = H[(size_t)s2 * 32 + lane];
            float2 x3 = H[(size_t)s3 * 32 + lane];
            ax += w0 * x0.x; ay += w0 * x0.y;
            ax += w1 * x1.x; ay += w1 * x1.y;
            ax += w2 * x2.x; ay += w2 * x2.y;
            ax += w3 * x3.x; ay += w3 * x3.y;
        }
        for (; j < m; j++) {
            int   s0 = __shfl_sync(0xffffffffu, src, j);
            float w0 = __shfl_sync(0xffffffffu, w, j);
            float2 x0 = H[(size_t)s0 * 32 + lane];
            ax += w0 * x0.x; ay += w0 * x0.y;
        }
    }
    float2 bb = ((const float2*)bias)[lane];
    ax += bb.x; ay += bb.y;
    if (RELU) { ax = fmaxf(ax, 0.f); ay = fmaxf(ay, 0.f); }
    out[(size_t)node * 32 + lane] = make_float2(ax, ay);
}

// ---------------- launch -----------------------------------------------------
extern "C" void kernel_launch(void* const* d_in, const int* in_sizes, int n_in,
                              void* d_out, int out_size) {
    const float* x   = (const float*)d_in[0];
    const void*  ei  = d_in[1];
    const float* ew  = (const float*)d_in[2];
    const float* W1  = (const float*)d_in[3];
    const float* b1  = (const float*)d_in[4];
    const float* W2  = (const float*)d_in[5];
    const float* b2  = (const float*)d_in[6];
    float*       out = (float*)d_out;

    const int TPB = 256;
    int nBlocksN = (N_NODES + TPB - 1) / TPB;
    int nBlocksE = (N_EDGES + TPB - 1) / TPB;
    int gemmBlocks = (N_NODES + 127) / 128;
    int aggBlocks  = (N_NODES + 7) / 8;

    // CSR build (reused by both layers)
    detect_kernel<<<1, 32>>>((const int*)ei);
    init_kernel<<<nBlocksN, TPB>>>();
    deg_hist_kernel<<<nBlocksE, TPB>>>(ei, ew);
    dinv_kernel<<<nBlocksN, TPB>>>();
    scan1_kernel<<<NSB, 1024>>>();
    scan2_kernel<<<1, 128>>>();
    scan3_kernel<<<NSB, 1024>>>();
    reorder_kernel<<<nBlocksE, TPB>>>(ei, ew);
    convw_kernel<<<(IN_DIM * 64 + TPB - 1) / TPB, TPB>>>(W1, W2);

    // layer 1
    mma_gemm_kernel<IN_DIM, false><<<gemmBlocks, 128>>>(x);
    agg_kernel<true><<<aggBlocks, TPB>>>(b1, nullptr);

    // layer 2
    mma_gemm_kernel<HID_DIM, true><<<gemmBlocks, 128>>>(nullptr);
    agg_kernel<false><<<aggBlocks, TPB>>>(b2, (float2*)out);
}

// round 7
// speedup vs baseline: 1.3707x; 1.0779x over previous
#include <cuda_runtime.h>
#include <cuda_bf16.h>
#include <cstdint>
#include <cstring>

#define N_NODES 100000
#define N_EDGES 1600000
#define IN_DIM  512
#define HID_DIM 64
#define NSB ((N_NODES + 1023) / 1024)   // 98 scan blocks

// ---------------- scratch (static device globals: allocation-free) ----------
__device__ int   g_idx64;
__device__ float g_deg[N_NODES];
__device__ float g_dinv[N_NODES];
__device__ int   g_cnt[N_NODES];
__device__ int   g_rs[N_NODES + 1];
__device__ int   g_cur[N_NODES];
__device__ int   g_bsum[NSB];
__device__ int   g_boff[NSB];
__device__ int   g_src[N_EDGES];
__device__ float g_w[N_EDGES];
__device__ float g_h[(size_t)N_NODES * HID_DIM];   // GEMM output (both layers)
__device__ float g_h2[(size_t)N_NODES * HID_DIM];  // layer-1 agg output
// bf16 hi/lo split of W, stored [n][k] (B operand)
__device__ __nv_bfloat16 g_b1hi[64 * IN_DIM];
__device__ __nv_bfloat16 g_b1lo[64 * IN_DIM];
__device__ __nv_bfloat16 g_b2hi[64 * HID_DIM];
__device__ __nv_bfloat16 g_b2lo[64 * HID_DIM];

// ---------------- helpers -----------------------------------------------------
__device__ __forceinline__ uint32_t pkbf(__nv_bfloat16 a, __nv_bfloat16 b) {
    __nv_bfloat162 t = __halves2bfloat162(a, b);
    uint32_t u; memcpy(&u, &t, 4); return u;
}
__device__ __forceinline__ void mma_bf16(float* c, const uint32_t* a,
                                         uint32_t b0, uint32_t b1) {
    asm("mma.sync.aligned.m16n8k16.row.col.f32.bf16.bf16.f32 "
        "{%0,%1,%2,%3},{%4,%5,%6,%7},{%8,%9},{%0,%1,%2,%3};"
        : "+f"(c[0]), "+f"(c[1]), "+f"(c[2]), "+f"(c[3])
        : "r"(a[0]), "r"(a[1]), "r"(a[2]), "r"(a[3]), "r"(b0), "r"(b1));
}

__device__ __forceinline__ int load_idx(const void* ei, long long pos) {
    if (g_idx64) return (int)((const long long*)ei)[pos];
    return ((const int*)ei)[pos];
}

// ---------------- fused init: deg/cnt init + dtype detect + W split ----------
__global__ void init_kernel(const int* __restrict__ ei32,
                            const float* __restrict__ W1,
                            const float* __restrict__ W2) {
    int i = blockIdx.x * blockDim.x + threadIdx.x;
    if (i < N_NODES) { g_deg[i] = 1.0f; g_cnt[i] = 0; }  // self-loop weight 1
    // edge-index dtype detect: int64 (<2^31) => all odd 32-bit words zero
    if (blockIdx.x == 0 && threadIdx.x < 32) {
        int nz = 0;
#pragma unroll
        for (int j = 0; j < 4; j++) nz |= ei32[1 + 2 * (threadIdx.x * 4 + j)];
        unsigned b = __ballot_sync(0xffffffffu, nz != 0);
        if (threadIdx.x == 0) g_idx64 = (b == 0u) ? 1 : 0;
    }
    // W -> bf16 hi/lo, transposed to [n][k]
    if (i < IN_DIM * 64) {
        int k = i / 64, n = i % 64;
        float w = W1[i];
        __nv_bfloat16 h = __float2bfloat16(w);
        g_b1hi[n * IN_DIM + k] = h;
        g_b1lo[n * IN_DIM + k] = __float2bfloat16(w - __bfloat162float(h));
    }
    if (i < HID_DIM * 64) {
        int k = i / 64, n = i % 64;
        float w = W2[i];
        __nv_bfloat16 h = __float2bfloat16(w);
        g_b2hi[n * HID_DIM + k] = h;
        g_b2lo[n * HID_DIM + k] = __float2bfloat16(w - __bfloat162float(h));
    }
}

__global__ void deg_hist_kernel(const void* __restrict__ ei,
                                const float* __restrict__ ew) {
    int e = blockIdx.x * blockDim.x + threadIdx.x;
    if (e >= N_EDGES) return;
    int d = load_idx(ei, (long long)N_EDGES + e);
    if ((unsigned)d < (unsigned)N_NODES) {
        atomicAdd(&g_deg[d], ew[e]);
        atomicAdd(&g_cnt[d], 1);
    }
}

// scan phase 1 (block-local) + fused dinv
__global__ void scan1_kernel() {
    __shared__ int ws[32];
    int b = blockIdx.x, tid = threadIdx.x, lane = tid & 31, wid = tid >> 5;
    int i = b * 1024 + tid;
    if (i < N_NODES) {
        float d = g_deg[i];
        g_dinv[i] = (d > 0.0f) ? rsqrtf(d) : 0.0f;
    }
    int v = (i < N_NODES) ? g_cnt[i] : 0;
    int x = v;
#pragma unroll
    for (int off = 1; off < 32; off <<= 1) {
        int y = __shfl_up_sync(0xffffffffu, x, off);
        if (lane >= off) x += y;
    }
    if (lane == 31) ws[wid] = x;
    __syncthreads();
    if (wid == 0) {
        int s = ws[lane];
#pragma unroll
        for (int off = 1; off < 32; off <<= 1) {
            int y = __shfl_up_sync(0xffffffffu, s, off);
            if (lane >= off) s += y;
        }
        ws[lane] = s;
    }
    __syncthreads();
    int incl = x + (wid > 0 ? ws[wid - 1] : 0);
    if (i < N_NODES) g_rs[i] = incl - v;       // block-local exclusive
    if (tid == 1023) g_bsum[b] = incl;         // block total
}

__global__ void scan2_kernel() {
    __shared__ int ws[4];
    int tid = threadIdx.x, lane = tid & 31, wid = tid >> 5;
    int v = (tid < NSB) ? g_bsum[tid] : 0;
    int x = v;
#pragma unroll
    for (int off = 1; off < 32; off <<= 1) {
        int y = __shfl_up_sync(0xffffffffu, x, off);
        if (lane >= off) x += y;
    }
    if (lane == 31) ws[wid] = x;
    __syncthreads();
    if (tid == 0) {
        int a = 0;
        for (int j = 0; j < 4; j++) { int t = ws[j]; ws[j] = a; a += t; }
    }
    __syncthreads();
    int excl = x - v + ws[wid];
    if (tid < NSB) g_boff[tid] = excl;
    if (tid == NSB - 1) g_rs[N_NODES] = excl + v;
}

__global__ void scan3_kernel() {
    int i = blockIdx.x * 1024 + threadIdx.x;
    if (i < N_NODES) {
        int r = g_rs[i] + g_boff[blockIdx.x];
        g_rs[i] = r;
        g_cur[i] = r;
    }
}

__global__ void reorder_kernel(const void* __restrict__ ei,
                               const float* __restrict__ ew) {
    int e = blockIdx.x * blockDim.x + threadIdx.x;
    if (e >= N_EDGES) return;
    int s = load_idx(ei, e);
    int d = load_idx(ei, (long long)N_EDGES + e);
    if ((unsigned)d >= (unsigned)N_NODES) return;
    int p = atomicAdd(&g_cur[d], 1);
    if ((unsigned)s < (unsigned)N_NODES) {
        g_src[p] = s;
        g_w[p]   = g_dinv[s] * ew[e] * g_dinv[d];
    } else {
        g_src[p] = 0;
        g_w[p]   = 0.0f;
    }
}

// ---------------- bf16 mma GEMM: g_h[M,64] = X[M,K] @ W[K,64] ----------------
// 128 threads (4 warps), CTA tile 128 x 64. Warp: 32 rows (2 m16) x 64 cols
// (8 n8). K chunked by 32 (2 k16 steps). 3-pass bf16 hi/lo split:
// D = Ah*Bh + Ah*Bl + Al*Bh (fp32 accum). Split done ONCE at tile load.
// SMEM rows padded to 20 words (40 bf16) -> conflict-free fragment LDS.
template <int K, bool FROM_G_H2>
__global__ void __launch_bounds__(128) mma_gemm_kernel(
    const float* __restrict__ Xext) {
    __shared__ uint32_t ash[128][20];
    __shared__ uint32_t asl[128][20];
    __shared__ uint32_t bsh[64][20];
    __shared__ uint32_t bsl[64][20];

    const float* X = FROM_G_H2 ? (const float*)g_h2 : Xext;
    const __nv_bfloat16* Bhi = (K == IN_DIM) ? g_b1hi : g_b2hi;  // device-side select
    const __nv_bfloat16* Blo = (K == IN_DIM) ? g_b1lo : g_b2lo;

    const int M = N_NODES;
    int t = threadIdx.x, wid = t >> 5, lane = t & 31;
    int g = lane >> 2, tig = lane & 3;
    int rowBase = blockIdx.x * 128;

    float acc[2][8][4] = {};

    for (int ch = 0; ch < K / 32; ch++) {
        int k0 = ch * 32;
        __syncthreads();
        // A tile: 128 rows x 32 k fp32 -> bf16 hi/lo (coalesced float4 LDG)
#pragma unroll
        for (int it = 0; it < 8; it++) {
            int id = t + it * 128;
            int row = id >> 3, q = id & 7;     // 8 quads per row
            int gr = rowBase + row;
            float4 v = make_float4(0.f, 0.f, 0.f, 0.f);
            if (gr < M) v = *(const float4*)(X + (size_t)gr * K + k0 + q * 4);
            __nv_bfloat16 hx = __float2bfloat16(v.x), hy = __float2bfloat16(v.y);
            __nv_bfloat16 hz = __float2bfloat16(v.z), hw = __float2bfloat16(v.w);
            uint32_t h0 = pkbf(hx, hy), h1 = pkbf(hz, hw);
            uint32_t l0 = pkbf(__float2bfloat16(v.x - __bfloat162float(hx)),
                               __float2bfloat16(v.y - __bfloat162float(hy)));
            uint32_t l1 = pkbf(__float2bfloat16(v.z - __bfloat162float(hz)),
                               __float2bfloat16(v.w - __bfloat162float(hw)));
            ash[row][q * 2] = h0; ash[row][q * 2 + 1] = h1;
            asl[row][q * 2] = l0; asl[row][q * 2 + 1] = l1;
        }
        // B tile: 64 n x 32 k bf16 hi/lo (pre-split in global), uint4 copy
#pragma unroll
        for (int it = 0; it < 2; it++) {
            int id = t + it * 128;
            int n = id >> 2, u = id & 3;
            *(uint4*)&bsh[n][u * 4] = *(const uint4*)(Bhi + (size_t)n * K + k0 + u * 8);
            *(uint4*)&bsl[n][u * 4] = *(const uint4*)(Blo + (size_t)n * K + k0 + u * 8);
        }
        __syncthreads();

#pragma unroll
        for (int ks = 0; ks < 2; ks++) {
            int w0 = tig + 8 * ks;       // cols 2t,2t+1 of this k16 block
            int w1 = tig + 4 + 8 * ks;   // cols 8+2t, 8+2t+1
            uint32_t ah[2][4], al[2][4];
#pragma unroll
            for (int mt = 0; mt < 2; mt++) {
                int r = wid * 32 + mt * 16 + g;
                ah[mt][0] = ash[r][w0];     ah[mt][1] = ash[r + 8][w0];
                ah[mt][2] = ash[r][w1];     ah[mt][3] = ash[r + 8][w1];
                al[mt][0] = asl[r][w0];     al[mt][1] = asl[r + 8][w0];
                al[mt][2] = asl[r][w1];     al[mt][3] = asl[r + 8][w1];
            }
#pragma unroll
            for (int nt = 0; nt < 8; nt++) {
                int n = nt * 8 + g;
                uint32_t bh0 = bsh[n][w0], bh1 = bsh[n][w1];
                uint32_t bl0 = bsl[n][w0], bl1 = bsl[n][w1];
#pragma unroll
                for (int mt = 0; mt < 2; mt++) {
                    mma_bf16(acc[mt][nt], ah[mt], bh0, bh1);
                    mma_bf16(acc[mt][nt], ah[mt], bl0, bl1);
                    mma_bf16(acc[mt][nt], al[mt], bh0, bh1);
                }
            }
        }
    }
    // epilogue: c0,c1 -> row g cols 2t,2t+1 ; c2,c3 -> row g+8
#pragma unroll
    for (int mt = 0; mt < 2; mt++) {
        int r0g = rowBase + wid * 32 + mt * 16 + g;
#pragma unroll
        for (int nt = 0; nt < 8; nt++) {
            int col = nt * 8 + tig * 2;
            if (r0g < M)
                *(float2*)(g_h + (size_t)r0g * 64 + col) =
                    make_float2(acc[mt][nt][0], acc[mt][nt][1]);
            if (r0g + 8 < M)
                *(float2*)(g_h + (size_t)(r0g + 8) * 64 + col) =
                    make_float2(acc[mt][nt][2], acc[mt][nt][3]);
        }
    }
}

// ---------------- aggregation: warp per node, CSR gather, no atomics --------
template <bool RELU>
__global__ void __launch_bounds__(256) agg_kernel(
    const float* __restrict__ bias, float2* __restrict__ outp) {
    const float2* H = (const float2*)g_h;
    float2* out = RELU ? (float2*)g_h2 : outp;

    int gw   = (blockIdx.x * blockDim.x + threadIdx.x) >> 5;
    int lane = threadIdx.x & 31;
    if (gw >= N_NODES) return;
    int node = gw;

    float di = g_dinv[node];
    float sn = di * di;
    float2 hv = H[(size_t)node * 32 + lane];
    float ax = sn * hv.x, ay = sn * hv.y;

    int b = g_rs[node], en = g_rs[node + 1];
    for (int i = b; i < en; i += 32) {
        int rem = en - i;
        int src = 0; float w = 0.f;
        if (lane < rem) { src = g_src[i + lane]; w = g_w[i + lane]; }
        int m = rem < 32 ? rem : 32;
        int j = 0;
        for (; j + 4 <= m; j += 4) {
            int   s0 = __shfl_sync(0xffffffffu, src, j);
            int   s1 = __shfl_sync(0xffffffffu, src, j + 1);
            int   s2 = __shfl_sync(0xffffffffu, src, j + 2);
            int   s3 = __shfl_sync(0xffffffffu, src, j + 3);
            float w0 = __shfl_sync(0xffffffffu, w, j);
            float w1 = __shfl_sync(0xffffffffu, w, j + 1);
            float w2 = __shfl_sync(0xffffffffu, w, j + 2);
            float w3 = __shfl_sync(0xffffffffu, w, j + 3);
            float2 x0 = H[(size_t)s0 * 32 + lane];
            float2 x1 = H[(size_t)s1 * 32 + lane];
            float2 x2 = H[(size_t)s2 * 32 + lane];
            float2 x3 = H[(size_t)s3 * 32 + lane];
            ax += w0 * x0.x; ay += w0 * x0.y;
            ax += w1 * x1.x; ay += w1 * x1.y;
            ax += w2 * x2.x; ay += w2 * x2.y;
            ax += w3 * x3.x; ay += w3 * x3.y;
        }
        for (; j < m; j++) {
            int   s0 = __shfl_sync(0xffffffffu, src, j);
            float w0 = __shfl_sync(0xffffffffu, w, j);
            float2 x0 = H[(size_t)s0 * 32 + lane];
            ax += w0 * x0.x; ay += w0 * x0.y;
        }
    }
    float2 bb = ((const float2*)bias)[lane];
    ax += bb.x; ay += bb.y;
    if (RELU) { ax = fmaxf(ax, 0.f); ay = fmaxf(ay, 0.f); }
    out[(size_t)node * 32 + lane] = make_float2(ax, ay);
}

// ---------------- launch -----------------------------------------------------
extern "C" void kernel_launch(void* const* d_in, const int* in_sizes, int n_in,
                              void* d_out, int out_size) {
    const float* x   = (const float*)d_in[0];
    const void*  ei  = d_in[1];
    const float* ew  = (const float*)d_in[2];
    const float* W1  = (const float*)d_in[3];
    const float* b1  = (const float*)d_in[4];
    const float* W2  = (const float*)d_in[5];
    const float* b2  = (const float*)d_in[6];
    float*       out = (float*)d_out;

    const int TPB = 256;
    int nBlocksN = (N_NODES + TPB - 1) / TPB;
    int nBlocksE = (N_EDGES + TPB - 1) / TPB;
    int gemmBlocks = (N_NODES + 127) / 128;
    int aggBlocks  = (N_NODES + 7) / 8;

    // CSR build (reused by both layers) — 6 launches
    init_kernel<<<nBlocksN, TPB>>>((const int*)ei, W1, W2);
    deg_hist_kernel<<<nBlocksE, TPB>>>(ei, ew);
    scan1_kernel<<<NSB, 1024>>>();
    scan2_kernel<<<1, 128>>>();
    scan3_kernel<<<NSB, 1024>>>();
    reorder_kernel<<<nBlocksE, TPB>>>(ei, ew);

    // layer 1
    mma_gemm_kernel<IN_DIM, false><<<gemmBlocks, 128>>>(x);
    agg_kernel<true><<<aggBlocks, TPB>>>(b1, nullptr);

    // layer 2
    mma_gemm_kernel<HID_DIM, true><<<gemmBlocks, 128>>>(nullptr);
    agg_kernel<false><<<aggBlocks, TPB>>>(b2, (float2*)out);
}